// round 10
// baseline (speedup 1.0000x reference)
#include <cuda_runtime.h>
#include <cstdint>
#include <math.h>

// ---------------- problem constants ----------------
#define NB    8
#define NTOK  4096
#define NCH   1024
#define NH    16
#define NL    64
#define ND    64
#define NCHK  32
#define MSEL  (NB*NCHK*64)        // 16384 selected rows
#define MFULL (NB*NTOK)           // 32768

// ---------------- scratch (device globals) -------------------------------
__device__ float g_Kh[(size_t)MSEL*NCH];
__device__ float g_Vh[(size_t)MSEL*NCH];
__device__ float g_G [(size_t)MFULL*NCH];     // gates (tf32-rounded)
__device__ float g_Ut[(size_t)NB*NCH*NCH];    // U^T: [b][c][h*64+l], tf32
__device__ float g_attn_part[8*128*NL*ND];

// ---------------- helpers -------------------------------------------------
__device__ __forceinline__ float to_tf32(float x) {
    unsigned u;
    asm("cvt.rna.tf32.f32 %0, %1;" : "=r"(u) : "f"(x));
    return __uint_as_float(u);
}
__device__ __forceinline__ uint32_t rnau(uint32_t u) {
    uint32_t o;
    asm("cvt.rna.tf32.f32 %0, %1;" : "=r"(o) : "f"(__uint_as_float(u)));
    return o;
}

__device__ __forceinline__ uint32_t smem_u32(const void* p) {
    uint32_t a;
    asm("{ .reg .u64 t; cvta.to.shared.u64 t, %1; cvt.u32.u64 %0, t; }"
        : "=r"(a) : "l"(p));
    return a;
}

__device__ __forceinline__ void cp16(uint32_t dst, const float* src) {
    asm volatile("cp.async.cg.shared.global [%0], [%1], 16;"
                 :: "r"(dst), "l"(__cvta_generic_to_global(src)));
}

__device__ __forceinline__ void ldsm4(uint32_t* r, uint32_t a) {
    asm volatile("ldmatrix.sync.aligned.m8n8.x4.shared.b16 {%0,%1,%2,%3}, [%4];"
        : "=r"(r[0]), "=r"(r[1]), "=r"(r[2]), "=r"(r[3]) : "r"(a));
}
// ldmatrix + per-fragment RNA tf32 rounding (idempotent on tf32 inputs)
__device__ __forceinline__ void ldsm4r(uint32_t* r, uint32_t a) {
    ldsm4(r, a);
    r[0] = rnau(r[0]); r[1] = rnau(r[1]);
    r[2] = rnau(r[2]); r[3] = rnau(r[3]);
}

__device__ __forceinline__ void mma8(float* c,
    uint32_t a0, uint32_t a1, uint32_t a2, uint32_t a3,
    uint32_t b0, uint32_t b1)
{
    asm volatile(
        "mma.sync.aligned.m16n8k8.row.col.f32.tf32.tf32.f32 "
        "{%0,%1,%2,%3}, {%4,%5,%6,%7}, {%8,%9}, {%0,%1,%2,%3};"
        : "+f"(c[0]), "+f"(c[1]), "+f"(c[2]), "+f"(c[3])
        : "r"(a0), "r"(a1), "r"(a2), "r"(a3), "r"(b0), "r"(b1));
}

// ---------------- tf32 NT GEMM: C[m,n] = sum_k A[map(m),k] * W[n,k] -------
// Block 128x128, 256 threads, warps 2(m) x 4(n), warp tile 64x32.
// KC=32 per stage, 3-stage cp.async ring, ONE barrier per iteration.
// Inputs are RAW fp32; RNA-tf32 rounding applied per fragment.
// MODE: 1 remap rows, 2 remap + rope epilogue, 3 batched (z = b),
//       4 plain + fused gates-softmax epilogue.
#define STG 32768        // stage bytes: A 128*128 + B 128*128

template<int MODE>
__global__ void __launch_bounds__(256, 2) gemm_tc(
    const float* __restrict__ A, const float* __restrict__ W,
    float* __restrict__ C)
{
    extern __shared__ char smem[];
    const uint32_t sb = smem_u32(smem);

    const int tid  = threadIdx.x;
    const int lane = tid & 31, warp = tid >> 5;
    const int wm   = warp & 1;            // 0..1  (m)
    const int wn   = warp >> 1;           // 0..3  (n)
    const int n0   = blockIdx.x * 128;
    const int m0   = blockIdx.y * 128;
    const int zb   = (MODE == 3) ? blockIdx.z : 0;
    const int moff = (MODE == 3) ? zb * 4096 : 0;
    const float* Wb = (MODE == 3) ? (W + (size_t)zb * 1048576u) : W;

    // ---- loader: each thread owns half an A row and half a B row
    const int lrow = tid >> 1;            // 0..127
    const int lc0  = (tid & 1) * 4;       // chunks 0..3 or 4..7
    int gm = m0 + lrow;
    if (MODE == 1 || MODE == 2) gm = ((gm >> 6) << 7) + (gm & 63);
    const float* Arow = A + (size_t)(moff + gm) * NCH;
    const float* Brow = Wb + (size_t)(n0 + lrow) * NCH;
    const uint32_t adst = sb + (uint32_t)lrow * 128u;
    const uint32_t bdst = sb + 16384u + (uint32_t)lrow * 128u;
    const uint32_t lswz = (uint32_t)(lrow & 7);

    // ---- ldmatrix per-lane precompute
    const int mq = lane >> 3, lr = lane & 7;
    const int aRow = wm*64 + ((mq & 1) << 3) + lr;
    const int aCp  = mq >> 1;
    const uint32_t aSwz = (uint32_t)(aRow & 7);
    const uint32_t aB = sb + (uint32_t)aRow * 128u;
    const int bRow = wn*32 + ((mq >> 1) << 3) + lr;
    const int bCp  = mq & 1;
    const uint32_t bSwz = (uint32_t)(bRow & 7);
    const uint32_t bB = sb + 16384u + (uint32_t)bRow * 128u;

    float acc[4][4][4];
    #pragma unroll
    for (int i = 0; i < 4; ++i)
        #pragma unroll
        for (int j = 0; j < 4; ++j)
            #pragma unroll
            for (int k = 0; k < 4; ++k) acc[i][j][k] = 0.f;

    // ---- prologue: stages 0..1
    #pragma unroll
    for (int s = 0; s < 2; ++s) {
        const int k0 = s * 32;
        const uint32_t so = (uint32_t)s * STG;
        #pragma unroll
        for (int c = 0; c < 4; ++c) {
            const uint32_t cc = (uint32_t)(lc0 + c);
            cp16(adst + so + ((cc ^ lswz) << 4), Arow + k0 + cc*4);
            cp16(bdst + so + ((cc ^ lswz) << 4), Brow + k0 + cc*4);
        }
        asm volatile("cp.async.commit_group;");
    }

    // ---- main loop
    uint32_t so_r = 0;
    uint32_t so_w = 2u * STG;
    for (int it = 0; it < 32; ++it) {
        asm volatile("cp.async.wait_group 1;");
        __syncthreads();

        if (it + 2 < 32) {
            const int k0 = (it + 2) * 32;
            #pragma unroll
            for (int c = 0; c < 4; ++c) {
                const uint32_t cc = (uint32_t)(lc0 + c);
                cp16(adst + so_w + ((cc ^ lswz) << 4), Arow + k0 + cc*4);
                cp16(bdst + so_w + ((cc ^ lswz) << 4), Brow + k0 + cc*4);
            }
        }
        asm volatile("cp.async.commit_group;");

        const uint32_t so = so_r;
        #pragma unroll
        for (int ks = 0; ks < 4; ++ks) {
            uint32_t af[4][4], bf[4][2];
            #pragma unroll
            for (int i = 0; i < 4; ++i)
                ldsm4r(af[i], aB + so + (uint32_t)i*2048u
                             + (((uint32_t)(ks*2 + aCp) ^ aSwz) << 4));
            #pragma unroll
            for (int p = 0; p < 2; ++p)
                ldsm4r(&bf[2*p][0], bB + so + (uint32_t)p*2048u
                             + (((uint32_t)(ks*2 + bCp) ^ bSwz) << 4));
            #pragma unroll
            for (int i = 0; i < 4; ++i)
                #pragma unroll
                for (int j = 0; j < 4; ++j)
                    mma8(acc[i][j], af[i][0], af[i][1], af[i][2], af[i][3],
                         bf[j][0], bf[j][1]);
        }

        so_r = (so_r == 2u*STG) ? 0u : so_r + STG;
        so_w = (so_w == 2u*STG) ? 0u : so_w + STG;
    }

    // ---- epilogue
    const int g = lane >> 2, q = lane & 3;
    if (MODE == 4) {
        asm volatile("cp.async.wait_group 0;");
        __syncthreads();
        float* eb = (float*)smem;                 // 128 x 132 floats
        #pragma unroll
        for (int i = 0; i < 4; ++i) {
            const int r = wm*64 + i*16 + g;
            #pragma unroll
            for (int j = 0; j < 4; ++j) {
                const int c = wn*32 + j*8 + 2*q;
                eb[r*132 + c]       = acc[i][j][0];
                eb[r*132 + c + 1]   = acc[i][j][1];
                eb[(r+8)*132 + c]   = acc[i][j][2];
                eb[(r+8)*132 + c+1] = acc[i][j][3];
            }
        }
        __syncthreads();
        const int row = tid >> 1, half = tid & 1;
        const float* src = eb + row*132 + half*64;
        float mx = -1e30f;
        #pragma unroll 8
        for (int k = 0; k < 64; ++k) mx = fmaxf(mx, src[k]);
        mx *= 0.125f;
        float e[64];
        float sm = 0.f;
        #pragma unroll 8
        for (int k = 0; k < 64; ++k) {
            e[k] = expf(src[k]*0.125f - mx);
            sm += e[k];
        }
        const float rs = 1.0f / sm;
        float* dst = C + (size_t)(m0 + row)*NCH + n0 + half*64;
        #pragma unroll
        for (int k4 = 0; k4 < 16; ++k4) {
            *(float4*)(dst + k4*4) = make_float4(
                to_tf32(e[k4*4+0]*rs), to_tf32(e[k4*4+1]*rs),
                to_tf32(e[k4*4+2]*rs), to_tf32(e[k4*4+3]*rs));
        }
        return;
    }
    #pragma unroll
    for (int i = 0; i < 4; ++i) {
        const int r = m0 + wm*64 + i*16 + g;
        if (MODE == 2) {
            const int t0 = (((r >> 6) & 31) << 7) + (r & 63);
            const int t1 = t0 + 8;
            #pragma unroll
            for (int j = 0; j < 4; ++j) {
                const int c = n0 + wn*32 + j*8 + 2*q;
                const int ip = (c & 63) >> 1;
                const float inv = expf(-(float)ip * 0.28782313662425572f);
                float s0, c0, s1, c1;
                sincosf((float)t0 * inv, &s0, &c0);
                sincosf((float)t1 * inv, &s1, &c1);
                const float a0 = acc[i][j][0], b0 = acc[i][j][1];
                const float a1 = acc[i][j][2], b1 = acc[i][j][3];
                *(float2*)&C[(size_t)r*NCH + c] =
                    make_float2(a0*c0 - b0*s0, a0*s0 + b0*c0);
                *(float2*)&C[(size_t)(r+8)*NCH + c] =
                    make_float2(a1*c1 - b1*s1, a1*s1 + b1*c1);
            }
        } else {
            #pragma unroll
            for (int j = 0; j < 4; ++j) {
                const int c = n0 + wn*32 + j*8 + 2*q;
                *(float2*)&C[(size_t)(moff + r)*NCH + c] =
                    make_float2(acc[i][j][0], acc[i][j][1]);
                *(float2*)&C[(size_t)(moff + r + 8)*NCH + c] =
                    make_float2(acc[i][j][2], acc[i][j][3]);
            }
        }
    }
}

// ---------------- attention core (tensor-core mma) ------------------------
// grid (8, 128), 256 threads (8 warps: 4 m-tiles x 2 n-halves).
// Per chunk: S = q@K^T (64x64x64), masked softmax, O += P@V.
#define ASTR 68
__global__ void __launch_bounds__(256, 2) attn_mma(
    const float* __restrict__ Kh, const float* __restrict__ Vh,
    const float* __restrict__ LQ, float* __restrict__ Part)
{
    extern __shared__ float smf[];
    float* qs = smf;                 // [64][68]  q  (l, d)
    float* Ks = smf + 64*ASTR;       // [64][68]  K  (c, d)
    float* Vt = smf + 2*64*ASTR;     // [64][68]  V^T (d, c)
    float* Ss = smf + 3*64*ASTR;     // [64][68]  S/P (l, c)

    const int tid  = threadIdx.x;
    const int lane = tid & 31, warp = tid >> 5;
    const int bh   = blockIdx.y;
    const int b    = bh >> 4, h = bh & 15;
    const int gx   = blockIdx.x;
    const int wm   = warp & 3;       // m-tile: rows wm*16
    const int wn   = warp >> 2;      // n-half: cols wn*32
    const int g    = lane >> 2, q = lane & 3;
    const int mr0  = wm*16;
    const int nb   = wn*32;

    // load q (once): qs[l][d]
    #pragma unroll
    for (int it = 0; it < 16; ++it) {
        int e = tid + it*256;
        int l = e >> 6, d = e & 63;
        qs[l*ASTR + d] = to_tf32(LQ[(size_t)(l*NH + h)*ND + d]);
    }

    float accO[4][4];
    #pragma unroll
    for (int j = 0; j < 4; ++j)
        #pragma unroll
        for (int k = 0; k < 4; ++k) accO[j][k] = 0.f;

    __syncthreads();

    for (int nn = 0; nn < 4; ++nn) {
        const int n = gx*4 + nn;
        const size_t rowbase = ((size_t)(b*NCHK + n)*64)*NCH + (size_t)h*ND;

        // load K natural, V transposed (tf32-rounded)
        #pragma unroll
        for (int it = 0; it < 16; ++it) {
            int e = tid + it*256;
            int c = e >> 6, d = e & 63;
            Ks[c*ASTR + d] = to_tf32(Kh[rowbase + (size_t)c*NCH + d]);
        }
        #pragma unroll
        for (int it = 0; it < 16; ++it) {
            int e = tid + it*256;
            int c = e >> 6, d = e & 63;
            Vt[d*ASTR + c] = to_tf32(Vh[rowbase + (size_t)c*NCH + d]);
        }
        __syncthreads();

        // S = q @ K^T  (m=l, n=c, k=d)
        float accS[4][4];
        #pragma unroll
        for (int j = 0; j < 4; ++j)
            #pragma unroll
            for (int k = 0; k < 4; ++k) accS[j][k] = 0.f;
        #pragma unroll
        for (int kk = 0; kk < 8; ++kk) {
            const int k0 = kk*8;
            const uint32_t a0 = __float_as_uint(qs[(mr0+g  )*ASTR + k0 + q]);
            const uint32_t a1 = __float_as_uint(qs[(mr0+g+8)*ASTR + k0 + q]);
            const uint32_t a2 = __float_as_uint(qs[(mr0+g  )*ASTR + k0 + q + 4]);
            const uint32_t a3 = __float_as_uint(qs[(mr0+g+8)*ASTR + k0 + q + 4]);
            #pragma unroll
            for (int j = 0; j < 4; ++j) {
                const int nr = nb + j*8 + g;
                const uint32_t b0 = __float_as_uint(Ks[nr*ASTR + k0 + q]);
                const uint32_t b1 = __float_as_uint(Ks[nr*ASTR + k0 + q + 4]);
                mma8(accS[j], a0, a1, a2, a3, b0, b1);
            }
        }
        // stage S*scale to Ss
        #pragma unroll
        for (int j = 0; j < 4; ++j) {
            const int c = nb + j*8 + 2*q;
            *(float2*)&Ss[(mr0+g  )*ASTR + c] =
                make_float2(accS[j][0]*0.125f, accS[j][1]*0.125f);
            *(float2*)&Ss[(mr0+g+8)*ASTR + c] =
                make_float2(accS[j][2]*0.125f, accS[j][3]*0.125f);
        }
        __syncthreads();

        // masked softmax per row (8 rows per warp), tf32-rounded P
        #pragma unroll
        for (int rr = 0; rr < 8; ++rr) {
            const int l = warp*8 + rr;
            float v0 = Ss[l*ASTR + lane];
            float v1 = Ss[l*ASTR + 32 + lane];
            const bool m0 = (lane <= l);
            const bool m1 = (32 + lane <= l);
            float mx = fmaxf(m0 ? v0 : -1e30f, m1 ? v1 : -1e30f);
            #pragma unroll
            for (int o = 16; o; o >>= 1) mx = fmaxf(mx, __shfl_xor_sync(~0u, mx, o));
            float e0 = m0 ? expf(v0 - mx) : 0.f;
            float e1 = m1 ? expf(v1 - mx) : 0.f;
            float sm = e0 + e1;
            #pragma unroll
            for (int o = 16; o; o >>= 1) sm += __shfl_xor_sync(~0u, sm, o);
            float r = 1.0f / sm;
            Ss[l*ASTR + lane]      = to_tf32(e0*r);
            Ss[l*ASTR + 32 + lane] = to_tf32(e1*r);
        }
        __syncthreads();

        // O += P @ V  (m=l, n=d, k=c); B = Vt[n=d][k=c]
        #pragma unroll
        for (int kk = 0; kk < 8; ++kk) {
            const int k0 = kk*8;
            const uint32_t a0 = __float_as_uint(Ss[(mr0+g  )*ASTR + k0 + q]);
            const uint32_t a1 = __float_as_uint(Ss[(mr0+g+8)*ASTR + k0 + q]);
            const uint32_t a2 = __float_as_uint(Ss[(mr0+g  )*ASTR + k0 + q + 4]);
            const uint32_t a3 = __float_as_uint(Ss[(mr0+g+8)*ASTR + k0 + q + 4]);
            #pragma unroll
            for (int j = 0; j < 4; ++j) {
                const int nr = nb + j*8 + g;
                const uint32_t b0 = __float_as_uint(Vt[nr*ASTR + k0 + q]);
                const uint32_t b1 = __float_as_uint(Vt[nr*ASTR + k0 + q + 4]);
                mma8(accO[j], a0, a1, a2, a3, b0, b1);
            }
        }
        __syncthreads();   // before next chunk overwrites Ks/Vt/Ss
    }

    // store partial O to Part[gx][bh][l][d]
    const size_t obase = ((size_t)(gx*128 + bh))*4096;
    #pragma unroll
    for (int j = 0; j < 4; ++j) {
        const int d = nb + j*8 + 2*q;
        *(float2*)&Part[obase + (mr0+g  )*64 + d] =
            make_float2(accO[j][0], accO[j][1]);
        *(float2*)&Part[obase + (mr0+g+8)*64 + d] =
            make_float2(accO[j][2], accO[j][3]);
    }
}

// ---------------- U kernel (fused partial reduce):
// Ut[b][c][h*64+l] = sum_d (sum_g Part[g][bh][l][d]) * Wp[c][h*64+d]
__global__ void __launch_bounds__(256) u_kernel(
    const float* __restrict__ Part, const float* __restrict__ Wp,
    float* __restrict__ Ut)
{
    extern __shared__ float us[];          // As 64x68 | Ws 128x68 (floats)
    float4* As4 = (float4*)us;             // stride 17 float4
    float4* Ws4 = (float4*)(us + 64*68);   // stride 17 float4

    const int tid  = threadIdx.x;
    const int cblk = blockIdx.x;
    const int bh   = blockIdx.y;
    const int b    = bh >> 4, h = bh & 15;

    const float4* Pf = (const float4*)Part;
    #pragma unroll
    for (int it = 0; it < 4; ++it) {
        int e = tid + it*256;              // 1024 float4 per bh
        int l = e >> 4, d4 = e & 15;
        float4 s = make_float4(0.f, 0.f, 0.f, 0.f);
        #pragma unroll
        for (int gp = 0; gp < 8; ++gp) {
            float4 v = Pf[(size_t)(gp*128 + bh)*1024 + e];
            s.x += v.x; s.y += v.y; s.z += v.z; s.w += v.w;
        }
        As4[l*17 + d4] = s;
    }
    const float4* Wf = (const float4*)Wp;
    #pragma unroll
    for (int it = 0; it < 8; ++it) {
        int e = tid + it*256;              // 2048 float4
        int cl = e >> 4, d4 = e & 15;
        Ws4[cl*17 + d4] = Wf[(size_t)(cblk*128 + cl)*256 + h*16 + d4];
    }
    __syncthreads();

    const int cg = tid >> 4;               // 0..15 (8 c each)
    const int lg = tid & 15;               // 0..15 (4 l each)
    float acc[8][4];
    #pragma unroll
    for (int i = 0; i < 8; ++i)
        #pragma unroll
        for (int j = 0; j < 4; ++j) acc[i][j] = 0.f;

    #pragma unroll 4
    for (int d4 = 0; d4 < 16; ++d4) {
        float4 a[4], w[8];
        #pragma unroll
        for (int j = 0; j < 4; ++j) a[j] = As4[(lg*4 + j)*17 + d4];
        #pragma unroll
        for (int i = 0; i < 8; ++i) w[i] = Ws4[(cg*8 + i)*17 + d4];
        #pragma unroll
        for (int i = 0; i < 8; ++i)
            #pragma unroll
            for (int j = 0; j < 4; ++j)
                acc[i][j] += w[i].x*a[j].x + w[i].y*a[j].y
                           + w[i].z*a[j].z + w[i].w*a[j].w;
    }

    #pragma unroll
    for (int i = 0; i < 8; ++i) {
        const int c = cblk*128 + cg*8 + i;
        #pragma unroll
        for (int j = 0; j < 4; ++j) {
            const int l = lg*4 + j;
            Ut[(size_t)b*1048576 + (size_t)c*1024 + h*64 + l] = to_tf32(acc[i][j]);
        }
    }
}

// ---------------- launch ---------------------------------------------------
extern "C" void kernel_launch(void* const* d_in, const int* in_sizes, int n_in,
                              void* d_out, int out_size)
{
    const float* x   = (const float*)d_in[0];
    const float* lq  = (const float*)d_in[1];
    const float* W_k = (const float*)d_in[2];
    const float* W_v = (const float*)d_in[3];
    const float* W_g = (const float*)d_in[4];
    const float* W_p = (const float*)d_in[5];
    float* out = (float*)d_out;

    float *Kh, *Vh, *G, *Ut, *Part;
    cudaGetSymbolAddress((void**)&Kh,   g_Kh);
    cudaGetSymbolAddress((void**)&Vh,   g_Vh);
    cudaGetSymbolAddress((void**)&G,    g_G);
    cudaGetSymbolAddress((void**)&Ut,   g_Ut);
    cudaGetSymbolAddress((void**)&Part, g_attn_part);

    const int SMEM = 3 * STG;   // 96 KB -> 2 CTAs/SM
    cudaFuncSetAttribute(gemm_tc<1>, cudaFuncAttributeMaxDynamicSharedMemorySize, SMEM);
    cudaFuncSetAttribute(gemm_tc<2>, cudaFuncAttributeMaxDynamicSharedMemorySize, SMEM);
    cudaFuncSetAttribute(gemm_tc<3>, cudaFuncAttributeMaxDynamicSharedMemorySize, SMEM);
    cudaFuncSetAttribute(gemm_tc<4>, cudaFuncAttributeMaxDynamicSharedMemorySize, SMEM);
    const int ASMEM = 4 * 64 * ASTR * 4;      // 69632 B -> 2 CTAs/SM
    cudaFuncSetAttribute(attn_mma, cudaFuncAttributeMaxDynamicSharedMemorySize, ASMEM);
    const int USMEM = (64*68 + 128*68) * 4;   // 52224 B
    cudaFuncSetAttribute(u_kernel, cudaFuncAttributeMaxDynamicSharedMemorySize, USMEM);

    // GEMMs (raw inputs; tf32 rounding fused into fragments)
    gemm_tc<4><<<dim3(8, 256), 256, SMEM>>>(x, W_g, G);   // gates (fused softmax)
    gemm_tc<2><<<dim3(8, 128), 256, SMEM>>>(x, W_k, Kh);  // K + rope
    gemm_tc<1><<<dim3(8, 128), 256, SMEM>>>(x, W_v, Vh);  // V

    // attention path (tensor-core)
    attn_mma<<<dim3(8, 128), 256, ASMEM>>>(Kh, Vh, lq, Part);
    u_kernel<<<dim3(8, 128), 256, USMEM>>>(Part, W_p, Ut);

    // out[b*4096+t][c] = sum_{hl} gates[row][hl] * Ut[b][c][hl]
    gemm_tc<3><<<dim3(8, 32, 8), 256, SMEM>>>(G, Ut, out);
}

// round 11
// speedup vs baseline: 1.1052x; 1.1052x over previous
#include <cuda_runtime.h>
#include <cstdint>
#include <math.h>

// ---------------- problem constants ----------------
#define NB    8
#define NTOK  4096
#define NCH   1024
#define NH    16
#define NL    64
#define ND    64
#define NCHK  32
#define MSEL  (NB*NCHK*64)        // 16384 selected rows
#define MFULL (NB*NTOK)           // 32768

// ---------------- scratch (device globals) -------------------------------
__device__ float g_Kh[(size_t)MSEL*NCH];
__device__ float g_Vh[(size_t)MSEL*NCH];
__device__ float g_G [(size_t)MFULL*NCH];     // gates (tf32-rounded)
__device__ float g_Ut[(size_t)NB*NCH*NCH];    // U^T: [b][c][h*64+l], tf32
__device__ float g_xr[(size_t)MFULL*NCH];     // RNA-rounded x
__device__ float g_Wr[3u*1024u*1024u];        // RNA-rounded W_k,W_v,W_g
__device__ float g_attn_part[8*128*NL*ND];

// ---------------- helpers -------------------------------------------------
__device__ __forceinline__ float to_tf32(float x) {
    unsigned u;
    asm("cvt.rna.tf32.f32 %0, %1;" : "=r"(u) : "f"(x));
    return __uint_as_float(u);
}

__device__ __forceinline__ uint32_t smem_u32(const void* p) {
    uint32_t a;
    asm("{ .reg .u64 t; cvta.to.shared.u64 t, %1; cvt.u32.u64 %0, t; }"
        : "=r"(a) : "l"(p));
    return a;
}

__device__ __forceinline__ void cp16(uint32_t dst, const float* src) {
    asm volatile("cp.async.cg.shared.global [%0], [%1], 16;"
                 :: "r"(dst), "l"(__cvta_generic_to_global(src)));
}

__device__ __forceinline__ void ldsm4(uint32_t* r, uint32_t a) {
    asm volatile("ldmatrix.sync.aligned.m8n8.x4.shared.b16 {%0,%1,%2,%3}, [%4];"
        : "=r"(r[0]), "=r"(r[1]), "=r"(r[2]), "=r"(r[3]) : "r"(a));
}

__device__ __forceinline__ void mma8(float* c,
    uint32_t a0, uint32_t a1, uint32_t a2, uint32_t a3,
    uint32_t b0, uint32_t b1)
{
    asm volatile(
        "mma.sync.aligned.m16n8k8.row.col.f32.tf32.tf32.f32 "
        "{%0,%1,%2,%3}, {%4,%5,%6,%7}, {%8,%9}, {%0,%1,%2,%3};"
        : "+f"(c[0]), "+f"(c[1]), "+f"(c[2]), "+f"(c[3])
        : "r"(a0), "r"(a1), "r"(a2), "r"(a3), "r"(b0), "r"(b1));
}

// ---------------- tf32 NT GEMM: C[m,n] = sum_k A[map(m),k] * W[n,k] -------
// Block 128x128, 256 threads, warps 2(m) x 4(n), warp tile 64x32.
// KC=32 per stage, 3-stage cp.async ring, ONE barrier per iteration.
// Inputs PRE-ROUNDED to tf32 (RNA).
// MODE: 1 remap rows, 2 remap + rope epilogue, 3 batched (z = b),
//       4 plain + fused gates-softmax epilogue.
#define STG 32768        // stage bytes: A 128*128 + B 128*128

template<int MODE>
__global__ void __launch_bounds__(256, 2) gemm_tc(
    const float* __restrict__ A, const float* __restrict__ W,
    float* __restrict__ C)
{
    extern __shared__ char smem[];
    const uint32_t sb = smem_u32(smem);

    const int tid  = threadIdx.x;
    const int lane = tid & 31, warp = tid >> 5;
    const int wm   = warp & 1;            // 0..1  (m)
    const int wn   = warp >> 1;           // 0..3  (n)
    const int n0   = blockIdx.x * 128;
    const int m0   = blockIdx.y * 128;
    const int zb   = (MODE == 3) ? blockIdx.z : 0;
    const int moff = (MODE == 3) ? zb * 4096 : 0;
    const float* Wb = (MODE == 3) ? (W + (size_t)zb * 1048576u) : W;

    // ---- loader: each thread owns half an A row and half a B row
    const int lrow = tid >> 1;            // 0..127
    const int lc0  = (tid & 1) * 4;       // chunks 0..3 or 4..7
    int gm = m0 + lrow;
    if (MODE == 1 || MODE == 2) gm = ((gm >> 6) << 7) + (gm & 63);
    const float* Arow = A + (size_t)(moff + gm) * NCH;
    const float* Brow = Wb + (size_t)(n0 + lrow) * NCH;
    const uint32_t adst = sb + (uint32_t)lrow * 128u;
    const uint32_t bdst = sb + 16384u + (uint32_t)lrow * 128u;
    const uint32_t lswz = (uint32_t)(lrow & 7);

    // ---- ldmatrix per-lane precompute
    const int mq = lane >> 3, lr = lane & 7;
    const int aRow = wm*64 + ((mq & 1) << 3) + lr;
    const int aCp  = mq >> 1;
    const uint32_t aSwz = (uint32_t)(aRow & 7);
    const uint32_t aB = sb + (uint32_t)aRow * 128u;
    const int bRow = wn*32 + ((mq >> 1) << 3) + lr;
    const int bCp  = mq & 1;
    const uint32_t bSwz = (uint32_t)(bRow & 7);
    const uint32_t bB = sb + 16384u + (uint32_t)bRow * 128u;

    float acc[4][4][4];
    #pragma unroll
    for (int i = 0; i < 4; ++i)
        #pragma unroll
        for (int j = 0; j < 4; ++j)
            #pragma unroll
            for (int k = 0; k < 4; ++k) acc[i][j][k] = 0.f;

    // ---- prologue: stages 0..1
    #pragma unroll
    for (int s = 0; s < 2; ++s) {
        const int k0 = s * 32;
        const uint32_t so = (uint32_t)s * STG;
        #pragma unroll
        for (int c = 0; c < 4; ++c) {
            const uint32_t cc = (uint32_t)(lc0 + c);
            cp16(adst + so + ((cc ^ lswz) << 4), Arow + k0 + cc*4);
            cp16(bdst + so + ((cc ^ lswz) << 4), Brow + k0 + cc*4);
        }
        asm volatile("cp.async.commit_group;");
    }

    // ---- main loop
    uint32_t so_r = 0;
    uint32_t so_w = 2u * STG;
    for (int it = 0; it < 32; ++it) {
        asm volatile("cp.async.wait_group 1;");
        __syncthreads();

        if (it + 2 < 32) {
            const int k0 = (it + 2) * 32;
            #pragma unroll
            for (int c = 0; c < 4; ++c) {
                const uint32_t cc = (uint32_t)(lc0 + c);
                cp16(adst + so_w + ((cc ^ lswz) << 4), Arow + k0 + cc*4);
                cp16(bdst + so_w + ((cc ^ lswz) << 4), Brow + k0 + cc*4);
            }
        }
        asm volatile("cp.async.commit_group;");

        const uint32_t so = so_r;
        #pragma unroll
        for (int ks = 0; ks < 4; ++ks) {
            uint32_t af[4][4], bf[4][2];
            #pragma unroll
            for (int i = 0; i < 4; ++i)
                ldsm4(af[i], aB + so + (uint32_t)i*2048u
                             + (((uint32_t)(ks*2 + aCp) ^ aSwz) << 4));
            #pragma unroll
            for (int p = 0; p < 2; ++p)
                ldsm4(&bf[2*p][0], bB + so + (uint32_t)p*2048u
                             + (((uint32_t)(ks*2 + bCp) ^ bSwz) << 4));
            #pragma unroll
            for (int i = 0; i < 4; ++i)
                #pragma unroll
                for (int j = 0; j < 4; ++j)
                    mma8(acc[i][j], af[i][0], af[i][1], af[i][2], af[i][3],
                         bf[j][0], bf[j][1]);
        }

        so_r = (so_r == 2u*STG) ? 0u : so_r + STG;
        so_w = (so_w == 2u*STG) ? 0u : so_w + STG;
    }

    // ---- epilogue
    const int g = lane >> 2, q = lane & 3;
    if (MODE == 4) {
        asm volatile("cp.async.wait_group 0;");
        __syncthreads();
        float* eb = (float*)smem;                 // 128 x 132 floats
        #pragma unroll
        for (int i = 0; i < 4; ++i) {
            const int r = wm*64 + i*16 + g;
            #pragma unroll
            for (int j = 0; j < 4; ++j) {
                const int c = wn*32 + j*8 + 2*q;
                eb[r*132 + c]       = acc[i][j][0];
                eb[r*132 + c + 1]   = acc[i][j][1];
                eb[(r+8)*132 + c]   = acc[i][j][2];
                eb[(r+8)*132 + c+1] = acc[i][j][3];
            }
        }
        __syncthreads();
        const int row = tid >> 1, half = tid & 1;
        const float* src = eb + row*132 + half*64;
        float mx = -1e30f;
        #pragma unroll 8
        for (int k = 0; k < 64; ++k) mx = fmaxf(mx, src[k]);
        mx *= 0.125f;
        float e[64];
        float sm = 0.f;
        #pragma unroll 8
        for (int k = 0; k < 64; ++k) {
            e[k] = expf(src[k]*0.125f - mx);
            sm += e[k];
        }
        const float rs = 1.0f / sm;
        float* dst = C + (size_t)(m0 + row)*NCH + n0 + half*64;
        #pragma unroll
        for (int k4 = 0; k4 < 16; ++k4) {
            *(float4*)(dst + k4*4) = make_float4(
                to_tf32(e[k4*4+0]*rs), to_tf32(e[k4*4+1]*rs),
                to_tf32(e[k4*4+2]*rs), to_tf32(e[k4*4+3]*rs));
        }
        return;
    }
    #pragma unroll
    for (int i = 0; i < 4; ++i) {
        const int r = m0 + wm*64 + i*16 + g;
        if (MODE == 2) {
            const int t0 = (((r >> 6) & 31) << 7) + (r & 63);
            const int t1 = t0 + 8;
            #pragma unroll
            for (int j = 0; j < 4; ++j) {
                const int c = n0 + wn*32 + j*8 + 2*q;
                const int ip = (c & 63) >> 1;
                const float inv = expf(-(float)ip * 0.28782313662425572f);
                float s0, c0, s1, c1;
                sincosf((float)t0 * inv, &s0, &c0);
                sincosf((float)t1 * inv, &s1, &c1);
                const float a0 = acc[i][j][0], b0 = acc[i][j][1];
                const float a1 = acc[i][j][2], b1 = acc[i][j][3];
                *(float2*)&C[(size_t)r*NCH + c] =
                    make_float2(a0*c0 - b0*s0, a0*s0 + b0*c0);
                *(float2*)&C[(size_t)(r+8)*NCH + c] =
                    make_float2(a1*c1 - b1*s1, a1*s1 + b1*c1);
            }
        } else {
            #pragma unroll
            for (int j = 0; j < 4; ++j) {
                const int c = n0 + wn*32 + j*8 + 2*q;
                *(float2*)&C[(size_t)(moff + r)*NCH + c] =
                    make_float2(acc[i][j][0], acc[i][j][1]);
                *(float2*)&C[(size_t)(moff + r + 8)*NCH + c] =
                    make_float2(acc[i][j][2], acc[i][j][3]);
            }
        }
    }
}

// ---------------- RNA tf32 pre-rounding ----------------------------------
__global__ void __launch_bounds__(256) round_tf32_k(
    const float4* __restrict__ in, float4* __restrict__ out, int n4)
{
    int i = blockIdx.x*256 + threadIdx.x;
    if (i < n4) {
        float4 v = in[i];
        v.x = to_tf32(v.x); v.y = to_tf32(v.y);
        v.z = to_tf32(v.z); v.w = to_tf32(v.w);
        out[i] = v;
    }
}

// ---------------- attention core (tensor-core mma) ------------------------
// grid (8, 128), 256 threads (8 warps: 4 m-tiles x 2 n-halves).
#define ASTR 68
__global__ void __launch_bounds__(256, 2) attn_mma(
    const float* __restrict__ Kh, const float* __restrict__ Vh,
    const float* __restrict__ LQ, float* __restrict__ Part)
{
    extern __shared__ float smf[];
    float* qs = smf;                 // [64][68]  q  (l, d)
    float* Ks = smf + 64*ASTR;       // [64][68]  K  (c, d)
    float* Vt = smf + 2*64*ASTR;     // [64][68]  V^T (d, c)
    float* Ss = smf + 3*64*ASTR;     // [64][68]  S/P (l, c)

    const int tid  = threadIdx.x;
    const int lane = tid & 31, warp = tid >> 5;
    const int bh   = blockIdx.y;
    const int b    = bh >> 4, h = bh & 15;
    const int gx   = blockIdx.x;
    const int wm   = warp & 3;       // m-tile: rows wm*16
    const int wn   = warp >> 2;      // n-half: cols wn*32
    const int g    = lane >> 2, q = lane & 3;
    const int mr0  = wm*16;
    const int nb   = wn*32;

    #pragma unroll
    for (int it = 0; it < 16; ++it) {
        int e = tid + it*256;
        int l = e >> 6, d = e & 63;
        qs[l*ASTR + d] = to_tf32(LQ[(size_t)(l*NH + h)*ND + d]);
    }

    float accO[4][4];
    #pragma unroll
    for (int j = 0; j < 4; ++j)
        #pragma unroll
        for (int k = 0; k < 4; ++k) accO[j][k] = 0.f;

    __syncthreads();

    for (int nn = 0; nn < 4; ++nn) {
        const int n = gx*4 + nn;
        const size_t rowbase = ((size_t)(b*NCHK + n)*64)*NCH + (size_t)h*ND;

        #pragma unroll
        for (int it = 0; it < 16; ++it) {
            int e = tid + it*256;
            int c = e >> 6, d = e & 63;
            Ks[c*ASTR + d] = to_tf32(Kh[rowbase + (size_t)c*NCH + d]);
        }
        #pragma unroll
        for (int it = 0; it < 16; ++it) {
            int e = tid + it*256;
            int c = e >> 6, d = e & 63;
            Vt[d*ASTR + c] = to_tf32(Vh[rowbase + (size_t)c*NCH + d]);
        }
        __syncthreads();

        float accS[4][4];
        #pragma unroll
        for (int j = 0; j < 4; ++j)
            #pragma unroll
            for (int k = 0; k < 4; ++k) accS[j][k] = 0.f;
        #pragma unroll
        for (int kk = 0; kk < 8; ++kk) {
            const int k0 = kk*8;
            const uint32_t a0 = __float_as_uint(qs[(mr0+g  )*ASTR + k0 + q]);
            const uint32_t a1 = __float_as_uint(qs[(mr0+g+8)*ASTR + k0 + q]);
            const uint32_t a2 = __float_as_uint(qs[(mr0+g  )*ASTR + k0 + q + 4]);
            const uint32_t a3 = __float_as_uint(qs[(mr0+g+8)*ASTR + k0 + q + 4]);
            #pragma unroll
            for (int j = 0; j < 4; ++j) {
                const int nr = nb + j*8 + g;
                const uint32_t b0 = __float_as_uint(Ks[nr*ASTR + k0 + q]);
                const uint32_t b1 = __float_as_uint(Ks[nr*ASTR + k0 + q + 4]);
                mma8(accS[j], a0, a1, a2, a3, b0, b1);
            }
        }
        #pragma unroll
        for (int j = 0; j < 4; ++j) {
            const int c = nb + j*8 + 2*q;
            *(float2*)&Ss[(mr0+g  )*ASTR + c] =
                make_float2(accS[j][0]*0.125f, accS[j][1]*0.125f);
            *(float2*)&Ss[(mr0+g+8)*ASTR + c] =
                make_float2(accS[j][2]*0.125f, accS[j][3]*0.125f);
        }
        __syncthreads();

        #pragma unroll
        for (int rr = 0; rr < 8; ++rr) {
            const int l = warp*8 + rr;
            float v0 = Ss[l*ASTR + lane];
            float v1 = Ss[l*ASTR + 32 + lane];
            const bool m0 = (lane <= l);
            const bool m1 = (32 + lane <= l);
            float mx = fmaxf(m0 ? v0 : -1e30f, m1 ? v1 : -1e30f);
            #pragma unroll
            for (int o = 16; o; o >>= 1) mx = fmaxf(mx, __shfl_xor_sync(~0u, mx, o));
            float e0 = m0 ? expf(v0 - mx) : 0.f;
            float e1 = m1 ? expf(v1 - mx) : 0.f;
            float sm = e0 + e1;
            #pragma unroll
            for (int o = 16; o; o >>= 1) sm += __shfl_xor_sync(~0u, sm, o);
            float r = 1.0f / sm;
            Ss[l*ASTR + lane]      = to_tf32(e0*r);
            Ss[l*ASTR + 32 + lane] = to_tf32(e1*r);
        }
        __syncthreads();

        #pragma unroll
        for (int kk = 0; kk < 8; ++kk) {
            const int k0 = kk*8;
            const uint32_t a0 = __float_as_uint(Ss[(mr0+g  )*ASTR + k0 + q]);
            const uint32_t a1 = __float_as_uint(Ss[(mr0+g+8)*ASTR + k0 + q]);
            const uint32_t a2 = __float_as_uint(Ss[(mr0+g  )*ASTR + k0 + q + 4]);
            const uint32_t a3 = __float_as_uint(Ss[(mr0+g+8)*ASTR + k0 + q + 4]);
            #pragma unroll
            for (int j = 0; j < 4; ++j) {
                const int nr = nb + j*8 + g;
                const uint32_t b0 = __float_as_uint(Vt[nr*ASTR + k0 + q]);
                const uint32_t b1 = __float_as_uint(Vt[nr*ASTR + k0 + q + 4]);
                mma8(accO[j], a0, a1, a2, a3, b0, b1);
            }
        }
        __syncthreads();
    }

    const size_t obase = ((size_t)(gx*128 + bh))*4096;
    #pragma unroll
    for (int j = 0; j < 4; ++j) {
        const int d = nb + j*8 + 2*q;
        *(float2*)&Part[obase + (mr0+g  )*64 + d] =
            make_float2(accO[j][0], accO[j][1]);
        *(float2*)&Part[obase + (mr0+g+8)*64 + d] =
            make_float2(accO[j][2], accO[j][3]);
    }
}

// ---------------- U kernel (fused partial reduce) --------------------------
__global__ void __launch_bounds__(256) u_kernel(
    const float* __restrict__ Part, const float* __restrict__ Wp,
    float* __restrict__ Ut)
{
    extern __shared__ float us[];          // As 64x68 | Ws 128x68 (floats)
    float4* As4 = (float4*)us;             // stride 17 float4
    float4* Ws4 = (float4*)(us + 64*68);   // stride 17 float4

    const int tid  = threadIdx.x;
    const int cblk = blockIdx.x;
    const int bh   = blockIdx.y;
    const int b    = bh >> 4, h = bh & 15;

    const float4* Pf = (const float4*)Part;
    #pragma unroll
    for (int it = 0; it < 4; ++it) {
        int e = tid + it*256;              // 1024 float4 per bh
        int l = e >> 4, d4 = e & 15;
        float4 s = make_float4(0.f, 0.f, 0.f, 0.f);
        #pragma unroll
        for (int gp = 0; gp < 8; ++gp) {
            float4 v = Pf[(size_t)(gp*128 + bh)*1024 + e];
            s.x += v.x; s.y += v.y; s.z += v.z; s.w += v.w;
        }
        As4[l*17 + d4] = s;
    }
    const float4* Wf = (const float4*)Wp;
    #pragma unroll
    for (int it = 0; it < 8; ++it) {
        int e = tid + it*256;              // 2048 float4
        int cl = e >> 4, d4 = e & 15;
        Ws4[cl*17 + d4] = Wf[(size_t)(cblk*128 + cl)*256 + h*16 + d4];
    }
    __syncthreads();

    const int cg = tid >> 4;               // 0..15 (8 c each)
    const int lg = tid & 15;               // 0..15 (4 l each)
    float acc[8][4];
    #pragma unroll
    for (int i = 0; i < 8; ++i)
        #pragma unroll
        for (int j = 0; j < 4; ++j) acc[i][j] = 0.f;

    #pragma unroll 4
    for (int d4 = 0; d4 < 16; ++d4) {
        float4 a[4], w[8];
        #pragma unroll
        for (int j = 0; j < 4; ++j) a[j] = As4[(lg*4 + j)*17 + d4];
        #pragma unroll
        for (int i = 0; i < 8; ++i) w[i] = Ws4[(cg*8 + i)*17 + d4];
        #pragma unroll
        for (int i = 0; i < 8; ++i)
            #pragma unroll
            for (int j = 0; j < 4; ++j)
                acc[i][j] += w[i].x*a[j].x + w[i].y*a[j].y
                           + w[i].z*a[j].z + w[i].w*a[j].w;
    }

    #pragma unroll
    for (int i = 0; i < 8; ++i) {
        const int c = cblk*128 + cg*8 + i;
        #pragma unroll
        for (int j = 0; j < 4; ++j) {
            const int l = lg*4 + j;
            Ut[(size_t)b*1048576 + (size_t)c*1024 + h*64 + l] = to_tf32(acc[i][j]);
        }
    }
}

// ---------------- launch ---------------------------------------------------
extern "C" void kernel_launch(void* const* d_in, const int* in_sizes, int n_in,
                              void* d_out, int out_size)
{
    const float* x   = (const float*)d_in[0];
    const float* lq  = (const float*)d_in[1];
    const float* W_k = (const float*)d_in[2];
    const float* W_v = (const float*)d_in[3];
    const float* W_g = (const float*)d_in[4];
    const float* W_p = (const float*)d_in[5];
    float* out = (float*)d_out;

    float *Kh, *Vh, *G, *Ut, *xr, *Wr, *Part;
    cudaGetSymbolAddress((void**)&Kh,   g_Kh);
    cudaGetSymbolAddress((void**)&Vh,   g_Vh);
    cudaGetSymbolAddress((void**)&G,    g_G);
    cudaGetSymbolAddress((void**)&Ut,   g_Ut);
    cudaGetSymbolAddress((void**)&xr,   g_xr);
    cudaGetSymbolAddress((void**)&Wr,   g_Wr);
    cudaGetSymbolAddress((void**)&Part, g_attn_part);

    const int SMEM = 3 * STG;   // 96 KB -> 2 CTAs/SM
    cudaFuncSetAttribute(gemm_tc<1>, cudaFuncAttributeMaxDynamicSharedMemorySize, SMEM);
    cudaFuncSetAttribute(gemm_tc<2>, cudaFuncAttributeMaxDynamicSharedMemorySize, SMEM);
    cudaFuncSetAttribute(gemm_tc<3>, cudaFuncAttributeMaxDynamicSharedMemorySize, SMEM);
    cudaFuncSetAttribute(gemm_tc<4>, cudaFuncAttributeMaxDynamicSharedMemorySize, SMEM);
    const int ASMEM = 4 * 64 * ASTR * 4;      // 69632 B -> 2 CTAs/SM
    cudaFuncSetAttribute(attn_mma, cudaFuncAttributeMaxDynamicSharedMemorySize, ASMEM);
    const int USMEM = (64*68 + 128*68) * 4;   // 52224 B
    cudaFuncSetAttribute(u_kernel, cudaFuncAttributeMaxDynamicSharedMemorySize, USMEM);

    // RNA pre-rounding (proven scheme)
    round_tf32_k<<<32768, 256>>>((const float4*)x,   (float4*)xr,               8388608);
    round_tf32_k<<<1024, 256>>>((const float4*)W_g, (float4*)(Wr + 2*1048576), 262144);
    round_tf32_k<<<1024, 256>>>((const float4*)W_k, (float4*)(Wr + 0*1048576), 262144);
    round_tf32_k<<<1024, 256>>>((const float4*)W_v, (float4*)(Wr + 1*1048576), 262144);

    // GEMMs
    gemm_tc<4><<<dim3(8, 256), 256, SMEM>>>(xr, Wr + 2*1048576, G);   // gates (fused softmax)
    gemm_tc<2><<<dim3(8, 128), 256, SMEM>>>(xr, Wr + 0*1048576, Kh);  // K + rope
    gemm_tc<1><<<dim3(8, 128), 256, SMEM>>>(xr, Wr + 1*1048576, Vh);  // V

    // attention path (tensor-core)
    attn_mma<<<dim3(8, 128), 256, ASMEM>>>(Kh, Vh, lq, Part);
    u_kernel<<<dim3(8, 128), 256, USMEM>>>(Part, W_p, Ut);

    // out[b*4096+t][c] = sum_{hl} gates[row][hl] * Ut[b][c][hl]
    gemm_tc<3><<<dim3(8, 32, 8), 256, SMEM>>>(G, Ut, out);
}

// round 12
// speedup vs baseline: 1.8727x; 1.6944x over previous
#include <cuda_runtime.h>
#include <cuda_fp16.h>
#include <cstdint>
#include <math.h>

// ---------------- problem constants ----------------
#define NB    8
#define NTOK  4096
#define NCH   1024
#define NH    16
#define NL    64
#define ND    64
#define NCHK  32
#define MSEL  (NB*NCHK*64)        // 16384 selected rows
#define MFULL (NB*NTOK)           // 32768

// ---------------- scratch (device globals) -------------------------------
__device__ float  g_Kh[(size_t)MSEL*NCH];
__device__ float  g_Vh[(size_t)MSEL*NCH];
__device__ __half g_Gh[(size_t)MFULL*NCH];     // gates, fp16
__device__ __half g_Uth[(size_t)NB*NCH*NCH];   // U^T: [b][c][h*64+l], fp16
__device__ __half g_xh[(size_t)MFULL*NCH];     // fp16 x
__device__ __half g_Wh[3u*1024u*1024u];        // fp16 W_k,W_v,W_g
__device__ float  g_attn_part[8*128*NL*ND];

// ---------------- helpers -------------------------------------------------
__device__ __forceinline__ float to_tf32(float x) {
    unsigned u;
    asm("cvt.rna.tf32.f32 %0, %1;" : "=r"(u) : "f"(x));
    return __uint_as_float(u);
}
__device__ __forceinline__ uint32_t h2b(__half2 h) {
    return *reinterpret_cast<uint32_t*>(&h);
}

__device__ __forceinline__ uint32_t smem_u32(const void* p) {
    uint32_t a;
    asm("{ .reg .u64 t; cvta.to.shared.u64 t, %1; cvt.u32.u64 %0, t; }"
        : "=r"(a) : "l"(p));
    return a;
}

__device__ __forceinline__ void cp16(uint32_t dst, const void* src) {
    asm volatile("cp.async.cg.shared.global [%0], [%1], 16;"
                 :: "r"(dst), "l"(__cvta_generic_to_global(src)));
}

__device__ __forceinline__ void ldsm4(uint32_t* r, uint32_t a) {
    asm volatile("ldmatrix.sync.aligned.m8n8.x4.shared.b16 {%0,%1,%2,%3}, [%4];"
        : "=r"(r[0]), "=r"(r[1]), "=r"(r[2]), "=r"(r[3]) : "r"(a));
}

// fp16 mma m16n8k16, fp32 accumulate
__device__ __forceinline__ void mma16(float* c,
    uint32_t a0, uint32_t a1, uint32_t a2, uint32_t a3,
    uint32_t b0, uint32_t b1)
{
    asm volatile(
        "mma.sync.aligned.m16n8k16.row.col.f32.f16.f16.f32 "
        "{%0,%1,%2,%3}, {%4,%5,%6,%7}, {%8,%9}, {%0,%1,%2,%3};"
        : "+f"(c[0]), "+f"(c[1]), "+f"(c[2]), "+f"(c[3])
        : "r"(a0), "r"(a1), "r"(a2), "r"(a3), "r"(b0), "r"(b1));
}

// tf32 mma (attention kernel)
__device__ __forceinline__ void mma8(float* c,
    uint32_t a0, uint32_t a1, uint32_t a2, uint32_t a3,
    uint32_t b0, uint32_t b1)
{
    asm volatile(
        "mma.sync.aligned.m16n8k8.row.col.f32.tf32.tf32.f32 "
        "{%0,%1,%2,%3}, {%4,%5,%6,%7}, {%8,%9}, {%0,%1,%2,%3};"
        : "+f"(c[0]), "+f"(c[1]), "+f"(c[2]), "+f"(c[3])
        : "r"(a0), "r"(a1), "r"(a2), "r"(a3), "r"(b0), "r"(b1));
}

// ---------------- fp16 NT GEMM: C[m,n] = sum_k A[map(m),k] * W[n,k] -------
// Block 128x128, 256 threads, warps 2(m) x 4(n), warp tile 64x32.
// KC=64 per stage (128 B/row of halves), 3-stage cp.async ring, 1 barrier/iter.
// MODE: 1 remap rows, 2 remap + rope epilogue, 3 batched (z = b),
//       4 plain + fused gates-softmax epilogue (fp16 gates out).
#define STG 32768        // stage bytes: A 128*128B + B 128*128B

template<int MODE>
__global__ void __launch_bounds__(256, 2) gemm_tc(
    const __half* __restrict__ A, const __half* __restrict__ W,
    float* __restrict__ C)
{
    extern __shared__ char smem[];
    const uint32_t sb = smem_u32(smem);

    const int tid  = threadIdx.x;
    const int lane = tid & 31, warp = tid >> 5;
    const int wm   = warp & 1;            // 0..1  (m)
    const int wn   = warp >> 1;           // 0..3  (n)
    const int n0   = blockIdx.x * 128;
    const int m0   = blockIdx.y * 128;
    const int zb   = (MODE == 3) ? blockIdx.z : 0;
    const int moff = (MODE == 3) ? zb * 4096 : 0;
    const __half* Wb = (MODE == 3) ? (W + (size_t)zb * 1048576u) : W;

    // ---- loader: each thread owns half an A row and half a B row
    const int lrow = tid >> 1;            // 0..127
    const int lc0  = (tid & 1) * 4;       // chunks 0..3 or 4..7 (16B = 8 halves)
    int gm = m0 + lrow;
    if (MODE == 1 || MODE == 2) gm = ((gm >> 6) << 7) + (gm & 63);
    const __half* Arow = A + (size_t)(moff + gm) * NCH;
    const __half* Brow = Wb + (size_t)(n0 + lrow) * NCH;
    const uint32_t adst = sb + (uint32_t)lrow * 128u;
    const uint32_t bdst = sb + 16384u + (uint32_t)lrow * 128u;
    const uint32_t lswz = (uint32_t)(lrow & 7);

    // ---- ldmatrix per-lane precompute (identical chunk math to tf32 ver)
    const int mq = lane >> 3, lr = lane & 7;
    const int aRow = wm*64 + ((mq & 1) << 3) + lr;
    const int aCp  = mq >> 1;
    const uint32_t aSwz = (uint32_t)(aRow & 7);
    const uint32_t aB = sb + (uint32_t)aRow * 128u;
    const int bRow = wn*32 + ((mq >> 1) << 3) + lr;
    const int bCp  = mq & 1;
    const uint32_t bSwz = (uint32_t)(bRow & 7);
    const uint32_t bB = sb + 16384u + (uint32_t)bRow * 128u;

    float acc[4][4][4];
    #pragma unroll
    for (int i = 0; i < 4; ++i)
        #pragma unroll
        for (int j = 0; j < 4; ++j)
            #pragma unroll
            for (int k = 0; k < 4; ++k) acc[i][j][k] = 0.f;

    // ---- prologue: stages 0..1 (KC=64 halves each)
    #pragma unroll
    for (int s = 0; s < 2; ++s) {
        const int k0 = s * 64;
        const uint32_t so = (uint32_t)s * STG;
        #pragma unroll
        for (int c = 0; c < 4; ++c) {
            const uint32_t cc = (uint32_t)(lc0 + c);
            cp16(adst + so + ((cc ^ lswz) << 4), Arow + k0 + cc*8);
            cp16(bdst + so + ((cc ^ lswz) << 4), Brow + k0 + cc*8);
        }
        asm volatile("cp.async.commit_group;");
    }

    // ---- main loop: 16 stages of KC=64
    uint32_t so_r = 0;
    uint32_t so_w = 2u * STG;
    for (int it = 0; it < 16; ++it) {
        asm volatile("cp.async.wait_group 1;");
        __syncthreads();

        if (it + 2 < 16) {
            const int k0 = (it + 2) * 64;
            #pragma unroll
            for (int c = 0; c < 4; ++c) {
                const uint32_t cc = (uint32_t)(lc0 + c);
                cp16(adst + so_w + ((cc ^ lswz) << 4), Arow + k0 + cc*8);
                cp16(bdst + so_w + ((cc ^ lswz) << 4), Brow + k0 + cc*8);
            }
        }
        asm volatile("cp.async.commit_group;");

        const uint32_t so = so_r;
        #pragma unroll
        for (int ks = 0; ks < 4; ++ks) {     // 4 k16-tiles per stage
            uint32_t af[4][4], bf[4][2];
            #pragma unroll
            for (int i = 0; i < 4; ++i)
                ldsm4(af[i], aB + so + (uint32_t)i*2048u
                             + (((uint32_t)(ks*2 + aCp) ^ aSwz) << 4));
            #pragma unroll
            for (int p = 0; p < 2; ++p)
                ldsm4(&bf[2*p][0], bB + so + (uint32_t)p*2048u
                             + (((uint32_t)(ks*2 + bCp) ^ bSwz) << 4));
            #pragma unroll
            for (int i = 0; i < 4; ++i)
                #pragma unroll
                for (int j = 0; j < 4; ++j)
                    mma16(acc[i][j], af[i][0], af[i][1], af[i][2], af[i][3],
                          bf[j][0], bf[j][1]);
        }

        so_r = (so_r == 2u*STG) ? 0u : so_r + STG;
        so_w = (so_w == 2u*STG) ? 0u : so_w + STG;
    }

    // ---- epilogue
    const int g = lane >> 2, q = lane & 3;
    if (MODE == 4) {
        asm volatile("cp.async.wait_group 0;");
        __syncthreads();
        float* eb = (float*)smem;                 // 128 x 132 floats
        #pragma unroll
        for (int i = 0; i < 4; ++i) {
            const int r = wm*64 + i*16 + g;
            #pragma unroll
            for (int j = 0; j < 4; ++j) {
                const int c = wn*32 + j*8 + 2*q;
                eb[r*132 + c]       = acc[i][j][0];
                eb[r*132 + c + 1]   = acc[i][j][1];
                eb[(r+8)*132 + c]   = acc[i][j][2];
                eb[(r+8)*132 + c+1] = acc[i][j][3];
            }
        }
        __syncthreads();
        const int row = tid >> 1, hh = tid & 1;
        const float* src = eb + row*132 + hh*64;
        float mx = -1e30f;
        #pragma unroll 8
        for (int k = 0; k < 64; ++k) mx = fmaxf(mx, src[k]);
        mx *= 0.125f;
        float e[64];
        float sm = 0.f;
        #pragma unroll 8
        for (int k = 0; k < 64; ++k) {
            e[k] = expf(src[k]*0.125f - mx);
            sm += e[k];
        }
        const float rs = 1.0f / sm;
        __half* Gh = reinterpret_cast<__half*>(C);
        __half* dst = Gh + (size_t)(m0 + row)*NCH + n0 + hh*64;
        #pragma unroll
        for (int k8 = 0; k8 < 8; ++k8) {
            uint4 u;
            u.x = h2b(__floats2half2_rn(e[k8*8+0]*rs, e[k8*8+1]*rs));
            u.y = h2b(__floats2half2_rn(e[k8*8+2]*rs, e[k8*8+3]*rs));
            u.z = h2b(__floats2half2_rn(e[k8*8+4]*rs, e[k8*8+5]*rs));
            u.w = h2b(__floats2half2_rn(e[k8*8+6]*rs, e[k8*8+7]*rs));
            *reinterpret_cast<uint4*>(dst + k8*8) = u;
        }
        return;
    }
    #pragma unroll
    for (int i = 0; i < 4; ++i) {
        const int r = m0 + wm*64 + i*16 + g;
        if (MODE == 2) {
            const int t0 = (((r >> 6) & 31) << 7) + (r & 63);
            const int t1 = t0 + 8;
            #pragma unroll
            for (int j = 0; j < 4; ++j) {
                const int c = n0 + wn*32 + j*8 + 2*q;
                const int ip = (c & 63) >> 1;
                const float inv = expf(-(float)ip * 0.28782313662425572f);
                float s0, c0, s1, c1;
                sincosf((float)t0 * inv, &s0, &c0);
                sincosf((float)t1 * inv, &s1, &c1);
                const float a0 = acc[i][j][0], b0 = acc[i][j][1];
                const float a1 = acc[i][j][2], b1 = acc[i][j][3];
                *(float2*)&C[(size_t)r*NCH + c] =
                    make_float2(a0*c0 - b0*s0, a0*s0 + b0*c0);
                *(float2*)&C[(size_t)(r+8)*NCH + c] =
                    make_float2(a1*c1 - b1*s1, a1*s1 + b1*c1);
            }
        } else {
            #pragma unroll
            for (int j = 0; j < 4; ++j) {
                const int c = n0 + wn*32 + j*8 + 2*q;
                *(float2*)&C[(size_t)(moff + r)*NCH + c] =
                    make_float2(acc[i][j][0], acc[i][j][1]);
                *(float2*)&C[(size_t)(moff + r + 8)*NCH + c] =
                    make_float2(acc[i][j][2], acc[i][j][3]);
            }
        }
    }
}

// ---------------- fp32 -> fp16 conversion ---------------------------------
__global__ void __launch_bounds__(256) conv_half(
    const float4* __restrict__ in, uint2* __restrict__ out, int n4)
{
    int i = blockIdx.x*256 + threadIdx.x;
    if (i < n4) {
        float4 v = in[i];
        uint2 o;
        o.x = h2b(__floats2half2_rn(v.x, v.y));
        o.y = h2b(__floats2half2_rn(v.z, v.w));
        out[i] = o;
    }
}

// ---------------- attention core (tensor-core mma, tf32) ------------------
#define ASTR 68
__global__ void __launch_bounds__(256, 2) attn_mma(
    const float* __restrict__ Kh, const float* __restrict__ Vh,
    const float* __restrict__ LQ, float* __restrict__ Part)
{
    extern __shared__ float smf[];
    float* qs = smf;                 // [64][68]  q  (l, d)
    float* Ks = smf + 64*ASTR;       // [64][68]  K  (c, d)
    float* Vt = smf + 2*64*ASTR;     // [64][68]  V^T (d, c)
    float* Ss = smf + 3*64*ASTR;     // [64][68]  S/P (l, c)

    const int tid  = threadIdx.x;
    const int lane = tid & 31, warp = tid >> 5;
    const int bh   = blockIdx.y;
    const int b    = bh >> 4, h = bh & 15;
    const int gx   = blockIdx.x;
    const int wm   = warp & 3;
    const int wn   = warp >> 2;
    const int g    = lane >> 2, q = lane & 3;
    const int mr0  = wm*16;
    const int nb   = wn*32;

    #pragma unroll
    for (int it = 0; it < 16; ++it) {
        int e = tid + it*256;
        int l = e >> 6, d = e & 63;
        qs[l*ASTR + d] = to_tf32(LQ[(size_t)(l*NH + h)*ND + d]);
    }

    float accO[4][4];
    #pragma unroll
    for (int j = 0; j < 4; ++j)
        #pragma unroll
        for (int k = 0; k < 4; ++k) accO[j][k] = 0.f;

    __syncthreads();

    for (int nn = 0; nn < 4; ++nn) {
        const int n = gx*4 + nn;
        const size_t rowbase = ((size_t)(b*NCHK + n)*64)*NCH + (size_t)h*ND;

        #pragma unroll
        for (int it = 0; it < 16; ++it) {
            int e = tid + it*256;
            int c = e >> 6, d = e & 63;
            Ks[c*ASTR + d] = to_tf32(Kh[rowbase + (size_t)c*NCH + d]);
        }
        #pragma unroll
        for (int it = 0; it < 16; ++it) {
            int e = tid + it*256;
            int c = e >> 6, d = e & 63;
            Vt[d*ASTR + c] = to_tf32(Vh[rowbase + (size_t)c*NCH + d]);
        }
        __syncthreads();

        float accS[4][4];
        #pragma unroll
        for (int j = 0; j < 4; ++j)
            #pragma unroll
            for (int k = 0; k < 4; ++k) accS[j][k] = 0.f;
        #pragma unroll
        for (int kk = 0; kk < 8; ++kk) {
            const int k0 = kk*8;
            const uint32_t a0 = __float_as_uint(qs[(mr0+g  )*ASTR + k0 + q]);
            const uint32_t a1 = __float_as_uint(qs[(mr0+g+8)*ASTR + k0 + q]);
            const uint32_t a2 = __float_as_uint(qs[(mr0+g  )*ASTR + k0 + q + 4]);
            const uint32_t a3 = __float_as_uint(qs[(mr0+g+8)*ASTR + k0 + q + 4]);
            #pragma unroll
            for (int j = 0; j < 4; ++j) {
                const int nr = nb + j*8 + g;
                const uint32_t b0 = __float_as_uint(Ks[nr*ASTR + k0 + q]);
                const uint32_t b1 = __float_as_uint(Ks[nr*ASTR + k0 + q + 4]);
                mma8(accS[j], a0, a1, a2, a3, b0, b1);
            }
        }
        #pragma unroll
        for (int j = 0; j < 4; ++j) {
            const int c = nb + j*8 + 2*q;
            *(float2*)&Ss[(mr0+g  )*ASTR + c] =
                make_float2(accS[j][0]*0.125f, accS[j][1]*0.125f);
            *(float2*)&Ss[(mr0+g+8)*ASTR + c] =
                make_float2(accS[j][2]*0.125f, accS[j][3]*0.125f);
        }
        __syncthreads();

        #pragma unroll
        for (int rr = 0; rr < 8; ++rr) {
            const int l = warp*8 + rr;
            float v0 = Ss[l*ASTR + lane];
            float v1 = Ss[l*ASTR + 32 + lane];
            const bool m0 = (lane <= l);
            const bool m1 = (32 + lane <= l);
            float mx = fmaxf(m0 ? v0 : -1e30f, m1 ? v1 : -1e30f);
            #pragma unroll
            for (int o = 16; o; o >>= 1) mx = fmaxf(mx, __shfl_xor_sync(~0u, mx, o));
            float e0 = m0 ? expf(v0 - mx) : 0.f;
            float e1 = m1 ? expf(v1 - mx) : 0.f;
            float sm = e0 + e1;
            #pragma unroll
            for (int o = 16; o; o >>= 1) sm += __shfl_xor_sync(~0u, sm, o);
            float r = 1.0f / sm;
            Ss[l*ASTR + lane]      = to_tf32(e0*r);
            Ss[l*ASTR + 32 + lane] = to_tf32(e1*r);
        }
        __syncthreads();

        #pragma unroll
        for (int kk = 0; kk < 8; ++kk) {
            const int k0 = kk*8;
            const uint32_t a0 = __float_as_uint(Ss[(mr0+g  )*ASTR + k0 + q]);
            const uint32_t a1 = __float_as_uint(Ss[(mr0+g+8)*ASTR + k0 + q]);
            const uint32_t a2 = __float_as_uint(Ss[(mr0+g  )*ASTR + k0 + q + 4]);
            const uint32_t a3 = __float_as_uint(Ss[(mr0+g+8)*ASTR + k0 + q + 4]);
            #pragma unroll
            for (int j = 0; j < 4; ++j) {
                const int nr = nb + j*8 + g;
                const uint32_t b0 = __float_as_uint(Vt[nr*ASTR + k0 + q]);
                const uint32_t b1 = __float_as_uint(Vt[nr*ASTR + k0 + q + 4]);
                mma8(accO[j], a0, a1, a2, a3, b0, b1);
            }
        }
        __syncthreads();
    }

    const size_t obase = ((size_t)(gx*128 + bh))*4096;
    #pragma unroll
    for (int j = 0; j < 4; ++j) {
        const int d = nb + j*8 + 2*q;
        *(float2*)&Part[obase + (mr0+g  )*64 + d] =
            make_float2(accO[j][0], accO[j][1]);
        *(float2*)&Part[obase + (mr0+g+8)*64 + d] =
            make_float2(accO[j][2], accO[j][3]);
    }
}

// ---------------- U kernel (fused partial reduce, fp16 out) ----------------
__global__ void __launch_bounds__(256) u_kernel(
    const float* __restrict__ Part, const float* __restrict__ Wp,
    __half* __restrict__ Ut)
{
    extern __shared__ float us[];          // As 64x68 | Ws 128x68 (floats)
    float4* As4 = (float4*)us;             // stride 17 float4
    float4* Ws4 = (float4*)(us + 64*68);   // stride 17 float4

    const int tid  = threadIdx.x;
    const int cblk = blockIdx.x;
    const int bh   = blockIdx.y;
    const int b    = bh >> 4, h = bh & 15;

    const float4* Pf = (const float4*)Part;
    #pragma unroll
    for (int it = 0; it < 4; ++it) {
        int e = tid + it*256;
        int l = e >> 4, d4 = e & 15;
        float4 s = make_float4(0.f, 0.f, 0.f, 0.f);
        #pragma unroll
        for (int gp = 0; gp < 8; ++gp) {
            float4 v = Pf[(size_t)(gp*128 + bh)*1024 + e];
            s.x += v.x; s.y += v.y; s.z += v.z; s.w += v.w;
        }
        As4[l*17 + d4] = s;
    }
    const float4* Wf = (const float4*)Wp;
    #pragma unroll
    for (int it = 0; it < 8; ++it) {
        int e = tid + it*256;
        int cl = e >> 4, d4 = e & 15;
        Ws4[cl*17 + d4] = Wf[(size_t)(cblk*128 + cl)*256 + h*16 + d4];
    }
    __syncthreads();

    const int cg = tid >> 4;
    const int lg = tid & 15;
    float acc[8][4];
    #pragma unroll
    for (int i = 0; i < 8; ++i)
        #pragma unroll
        for (int j = 0; j < 4; ++j) acc[i][j] = 0.f;

    #pragma unroll 4
    for (int d4 = 0; d4 < 16; ++d4) {
        float4 a[4], w[8];
        #pragma unroll
        for (int j = 0; j < 4; ++j) a[j] = As4[(lg*4 + j)*17 + d4];
        #pragma unroll
        for (int i = 0; i < 8; ++i) w[i] = Ws4[(cg*8 + i)*17 + d4];
        #pragma unroll
        for (int i = 0; i < 8; ++i)
            #pragma unroll
            for (int j = 0; j < 4; ++j)
                acc[i][j] += w[i].x*a[j].x + w[i].y*a[j].y
                           + w[i].z*a[j].z + w[i].w*a[j].w;
    }

    #pragma unroll
    for (int i = 0; i < 8; ++i) {
        const int c = cblk*128 + cg*8 + i;
        uint2 u;
        u.x = h2b(__floats2half2_rn(acc[i][0], acc[i][1]));
        u.y = h2b(__floats2half2_rn(acc[i][2], acc[i][3]));
        *reinterpret_cast<uint2*>(
            Ut + (size_t)b*1048576 + (size_t)c*1024 + h*64 + lg*4) = u;
    }
}

// ---------------- launch ---------------------------------------------------
extern "C" void kernel_launch(void* const* d_in, const int* in_sizes, int n_in,
                              void* d_out, int out_size)
{
    const float* x   = (const float*)d_in[0];
    const float* lq  = (const float*)d_in[1];
    const float* W_k = (const float*)d_in[2];
    const float* W_v = (const float*)d_in[3];
    const float* W_g = (const float*)d_in[4];
    const float* W_p = (const float*)d_in[5];
    float* out = (float*)d_out;

    float *Kh, *Vh, *Part;
    __half *Gh, *Uth, *xh, *Wh;
    cudaGetSymbolAddress((void**)&Kh,   g_Kh);
    cudaGetSymbolAddress((void**)&Vh,   g_Vh);
    cudaGetSymbolAddress((void**)&Gh,   g_Gh);
    cudaGetSymbolAddress((void**)&Uth,  g_Uth);
    cudaGetSymbolAddress((void**)&xh,   g_xh);
    cudaGetSymbolAddress((void**)&Wh,   g_Wh);
    cudaGetSymbolAddress((void**)&Part, g_attn_part);

    const int SMEM = 3 * STG;   // 96 KB -> 2 CTAs/SM
    cudaFuncSetAttribute(gemm_tc<1>, cudaFuncAttributeMaxDynamicSharedMemorySize, SMEM);
    cudaFuncSetAttribute(gemm_tc<2>, cudaFuncAttributeMaxDynamicSharedMemorySize, SMEM);
    cudaFuncSetAttribute(gemm_tc<3>, cudaFuncAttributeMaxDynamicSharedMemorySize, SMEM);
    cudaFuncSetAttribute(gemm_tc<4>, cudaFuncAttributeMaxDynamicSharedMemorySize, SMEM);
    const int ASMEM = 4 * 64 * ASTR * 4;      // 69632 B -> 2 CTAs/SM
    cudaFuncSetAttribute(attn_mma, cudaFuncAttributeMaxDynamicSharedMemorySize, ASMEM);
    const int USMEM = (64*68 + 128*68) * 4;   // 52224 B
    cudaFuncSetAttribute(u_kernel, cudaFuncAttributeMaxDynamicSharedMemorySize, USMEM);

    // fp32 -> fp16 conversion (RN; same 2^-11 budget as tf32 RNA)
    conv_half<<<32768, 256>>>((const float4*)x,   (uint2*)xh,               8388608);
    conv_half<<<1024, 256>>>((const float4*)W_g, (uint2*)(Wh + 2*1048576), 262144);
    conv_half<<<1024, 256>>>((const float4*)W_k, (uint2*)(Wh + 0*1048576), 262144);
    conv_half<<<1024, 256>>>((const float4*)W_v, (uint2*)(Wh + 1*1048576), 262144);

    // GEMMs (fp16 tensor cores)
    gemm_tc<4><<<dim3(8, 256), 256, SMEM>>>(xh, Wh + 2*1048576, (float*)Gh); // gates
    gemm_tc<2><<<dim3(8, 128), 256, SMEM>>>(xh, Wh + 0*1048576, Kh);         // K + rope
    gemm_tc<1><<<dim3(8, 128), 256, SMEM>>>(xh, Wh + 1*1048576, Vh);         // V

    // attention path (tf32 tensor-core, fp32 I/O)
    attn_mma<<<dim3(8, 128), 256, ASMEM>>>(Kh, Vh, lq, Part);
    u_kernel<<<dim3(8, 128), 256, USMEM>>>(Part, W_p, Uth);

    // out[b*4096+t][c] = sum_{hl} gates[row][hl] * Ut[b][c][hl]
    gemm_tc<3><<<dim3(8, 32, 8), 256, SMEM>>>(Gh, Uth, out);
}

// round 13
// speedup vs baseline: 1.9224x; 1.0265x over previous
#include <cuda_runtime.h>
#include <cuda_fp16.h>
#include <cstdint>
#include <math.h>

// ---------------- problem constants ----------------
#define NB    8
#define NTOK  4096
#define NCH   1024
#define NH    16
#define NL    64
#define ND    64
#define NCHK  32
#define MSEL  (NB*NCHK*64)
#define MFULL (NB*NTOK)

// ---------------- scratch (device globals) -------------------------------
__device__ __half g_Kh[(size_t)MSEL*NCH];      // rope'd K, fp16
__device__ __half g_Vh[(size_t)MSEL*NCH];      // V, fp16
__device__ __half g_Gh[(size_t)MFULL*NCH];     // gates, fp16
__device__ __half g_Uth[(size_t)NB*NCH*NCH];   // U^T: [b][c][h*64+l], fp16
__device__ __half g_xh[(size_t)MFULL*NCH];     // fp16 x
__device__ __half g_Wh[3u*1024u*1024u];        // fp16 W_k,W_v,W_g
__device__ float  g_attn_part[8*128*NL*ND];

// ---------------- helpers -------------------------------------------------
__device__ __forceinline__ uint32_t h2b(__half2 h) {
    return *reinterpret_cast<uint32_t*>(&h);
}

__device__ __forceinline__ uint32_t smem_u32(const void* p) {
    uint32_t a;
    asm("{ .reg .u64 t; cvta.to.shared.u64 t, %1; cvt.u32.u64 %0, t; }"
        : "=r"(a) : "l"(p));
    return a;
}

__device__ __forceinline__ void cp16(uint32_t dst, const void* src) {
    asm volatile("cp.async.cg.shared.global [%0], [%1], 16;"
                 :: "r"(dst), "l"(__cvta_generic_to_global(src)));
}

__device__ __forceinline__ void ldsm4(uint32_t* r, uint32_t a) {
    asm volatile("ldmatrix.sync.aligned.m8n8.x4.shared.b16 {%0,%1,%2,%3}, [%4];"
        : "=r"(r[0]), "=r"(r[1]), "=r"(r[2]), "=r"(r[3]) : "r"(a));
}

// fp16 mma m16n8k16, fp32 accumulate
__device__ __forceinline__ void mma16(float* c,
    uint32_t a0, uint32_t a1, uint32_t a2, uint32_t a3,
    uint32_t b0, uint32_t b1)
{
    asm volatile(
        "mma.sync.aligned.m16n8k16.row.col.f32.f16.f16.f32 "
        "{%0,%1,%2,%3}, {%4,%5,%6,%7}, {%8,%9}, {%0,%1,%2,%3};"
        : "+f"(c[0]), "+f"(c[1]), "+f"(c[2]), "+f"(c[3])
        : "r"(a0), "r"(a1), "r"(a2), "r"(a3), "r"(b0), "r"(b1));
}

// ---------------- fp16 NT GEMM --------------------------------------------
// Block 128x128, 256 threads, warps 2(m) x 4(n), warp tile 64x32.
// KC=64/stage, 3-stage cp.async ring, 1 barrier/iter, 2 CTAs/SM.
// MODE: 3 batched out (z=b, fp32 out), 4 gates+softmax (fp16 out),
//       5 merged K/V (z: 0=K+rope fp16, 1=V fp16), both remapped rows.
#define STG 32768

template<int MODE>
__global__ void __launch_bounds__(256, 2) gemm_tc(
    const __half* __restrict__ A, const __half* __restrict__ W,
    void* __restrict__ Cv, void* __restrict__ C2v)
{
    extern __shared__ char smem[];
    const uint32_t sb = smem_u32(smem);

    const int tid  = threadIdx.x;
    const int lane = tid & 31, warp = tid >> 5;
    const int wm   = warp & 1;
    const int wn   = warp >> 1;
    const int n0   = blockIdx.x * 128;
    const int m0   = blockIdx.y * 128;
    const int zb   = (MODE == 3 || MODE == 5) ? blockIdx.z : 0;
    const int moff = (MODE == 3) ? zb * 4096 : 0;
    const __half* Wb = (MODE == 3) ? (W + (size_t)zb * 1048576u)
                     : (MODE == 5) ? (W + (size_t)zb * 1048576u) : W;

    // ---- loader
    const int lrow = tid >> 1;
    const int lc0  = (tid & 1) * 4;
    int gm = m0 + lrow;
    if (MODE == 5) gm = ((gm >> 6) << 7) + (gm & 63);
    const __half* Arow = A + (size_t)(moff + gm) * NCH;
    const __half* Brow = Wb + (size_t)(n0 + lrow) * NCH;
    const uint32_t adst = sb + (uint32_t)lrow * 128u;
    const uint32_t bdst = sb + 16384u + (uint32_t)lrow * 128u;
    const uint32_t lswz = (uint32_t)(lrow & 7);

    // ---- ldmatrix per-lane precompute
    const int mq = lane >> 3, lr = lane & 7;
    const int aRow = wm*64 + ((mq & 1) << 3) + lr;
    const int aCp  = mq >> 1;
    const uint32_t aSwz = (uint32_t)(aRow & 7);
    const uint32_t aB = sb + (uint32_t)aRow * 128u;
    const int bRow = wn*32 + ((mq >> 1) << 3) + lr;
    const int bCp  = mq & 1;
    const uint32_t bSwz = (uint32_t)(bRow & 7);
    const uint32_t bB = sb + 16384u + (uint32_t)bRow * 128u;

    float acc[4][4][4];
    #pragma unroll
    for (int i = 0; i < 4; ++i)
        #pragma unroll
        for (int j = 0; j < 4; ++j)
            #pragma unroll
            for (int k = 0; k < 4; ++k) acc[i][j][k] = 0.f;

    // ---- prologue
    #pragma unroll
    for (int s = 0; s < 2; ++s) {
        const int k0 = s * 64;
        const uint32_t so = (uint32_t)s * STG;
        #pragma unroll
        for (int c = 0; c < 4; ++c) {
            const uint32_t cc = (uint32_t)(lc0 + c);
            cp16(adst + so + ((cc ^ lswz) << 4), Arow + k0 + cc*8);
            cp16(bdst + so + ((cc ^ lswz) << 4), Brow + k0 + cc*8);
        }
        asm volatile("cp.async.commit_group;");
    }

    // ---- main loop: 16 stages of KC=64
    uint32_t so_r = 0;
    uint32_t so_w = 2u * STG;
    for (int it = 0; it < 16; ++it) {
        asm volatile("cp.async.wait_group 1;");
        __syncthreads();

        if (it + 2 < 16) {
            const int k0 = (it + 2) * 64;
            #pragma unroll
            for (int c = 0; c < 4; ++c) {
                const uint32_t cc = (uint32_t)(lc0 + c);
                cp16(adst + so_w + ((cc ^ lswz) << 4), Arow + k0 + cc*8);
                cp16(bdst + so_w + ((cc ^ lswz) << 4), Brow + k0 + cc*8);
            }
        }
        asm volatile("cp.async.commit_group;");

        const uint32_t so = so_r;
        #pragma unroll
        for (int ks = 0; ks < 4; ++ks) {
            uint32_t af[4][4], bf[4][2];
            #pragma unroll
            for (int i = 0; i < 4; ++i)
                ldsm4(af[i], aB + so + (uint32_t)i*2048u
                             + (((uint32_t)(ks*2 + aCp) ^ aSwz) << 4));
            #pragma unroll
            for (int p = 0; p < 2; ++p)
                ldsm4(&bf[2*p][0], bB + so + (uint32_t)p*2048u
                             + (((uint32_t)(ks*2 + bCp) ^ bSwz) << 4));
            #pragma unroll
            for (int i = 0; i < 4; ++i)
                #pragma unroll
                for (int j = 0; j < 4; ++j)
                    mma16(acc[i][j], af[i][0], af[i][1], af[i][2], af[i][3],
                          bf[j][0], bf[j][1]);
        }

        so_r = (so_r == 2u*STG) ? 0u : so_r + STG;
        so_w = (so_w == 2u*STG) ? 0u : so_w + STG;
    }

    // ---- epilogue
    const int g = lane >> 2, q = lane & 3;
    if (MODE == 4) {
        asm volatile("cp.async.wait_group 0;");
        __syncthreads();
        float* eb = (float*)smem;
        #pragma unroll
        for (int i = 0; i < 4; ++i) {
            const int r = wm*64 + i*16 + g;
            #pragma unroll
            for (int j = 0; j < 4; ++j) {
                const int c = wn*32 + j*8 + 2*q;
                eb[r*132 + c]       = acc[i][j][0];
                eb[r*132 + c + 1]   = acc[i][j][1];
                eb[(r+8)*132 + c]   = acc[i][j][2];
                eb[(r+8)*132 + c+1] = acc[i][j][3];
            }
        }
        __syncthreads();
        const int row = tid >> 1, hh = tid & 1;
        const float* src = eb + row*132 + hh*64;
        float mx = -1e30f;
        #pragma unroll 8
        for (int k = 0; k < 64; ++k) mx = fmaxf(mx, src[k]);
        mx *= 0.125f;
        float e[64];
        float sm = 0.f;
        #pragma unroll 8
        for (int k = 0; k < 64; ++k) {
            e[k] = expf(src[k]*0.125f - mx);
            sm += e[k];
        }
        const float rs = 1.0f / sm;
        __half* dst = (__half*)Cv + (size_t)(m0 + row)*NCH + n0 + hh*64;
        #pragma unroll
        for (int k8 = 0; k8 < 8; ++k8) {
            uint4 u;
            u.x = h2b(__floats2half2_rn(e[k8*8+0]*rs, e[k8*8+1]*rs));
            u.y = h2b(__floats2half2_rn(e[k8*8+2]*rs, e[k8*8+3]*rs));
            u.z = h2b(__floats2half2_rn(e[k8*8+4]*rs, e[k8*8+5]*rs));
            u.w = h2b(__floats2half2_rn(e[k8*8+6]*rs, e[k8*8+7]*rs));
            *reinterpret_cast<uint4*>(dst + k8*8) = u;
        }
        return;
    }
    if (MODE == 5) {
        __half* Ch = (zb == 0) ? (__half*)Cv : (__half*)C2v;
        #pragma unroll
        for (int i = 0; i < 4; ++i) {
            const int r = m0 + wm*64 + i*16 + g;
            if (zb == 0) {
                const int t0 = (((r >> 6) & 31) << 7) + (r & 63);
                const int t1 = t0 + 8;
                #pragma unroll
                for (int j = 0; j < 4; ++j) {
                    const int c = n0 + wn*32 + j*8 + 2*q;
                    const int ip = (c & 63) >> 1;
                    const float inv = expf(-(float)ip * 0.28782313662425572f);
                    float s0, c0, s1, c1;
                    sincosf((float)t0 * inv, &s0, &c0);
                    sincosf((float)t1 * inv, &s1, &c1);
                    const float a0 = acc[i][j][0], b0 = acc[i][j][1];
                    const float a1 = acc[i][j][2], b1 = acc[i][j][3];
                    *reinterpret_cast<uint32_t*>(&Ch[(size_t)r*NCH + c]) =
                        h2b(__floats2half2_rn(a0*c0 - b0*s0, a0*s0 + b0*c0));
                    *reinterpret_cast<uint32_t*>(&Ch[(size_t)(r+8)*NCH + c]) =
                        h2b(__floats2half2_rn(a1*c1 - b1*s1, a1*s1 + b1*c1));
                }
            } else {
                #pragma unroll
                for (int j = 0; j < 4; ++j) {
                    const int c = n0 + wn*32 + j*8 + 2*q;
                    *reinterpret_cast<uint32_t*>(&Ch[(size_t)r*NCH + c]) =
                        h2b(__floats2half2_rn(acc[i][j][0], acc[i][j][1]));
                    *reinterpret_cast<uint32_t*>(&Ch[(size_t)(r+8)*NCH + c]) =
                        h2b(__floats2half2_rn(acc[i][j][2], acc[i][j][3]));
                }
            }
        }
        return;
    }
    // MODE 3: fp32 out, batched rows
    float* C = (float*)Cv;
    #pragma unroll
    for (int i = 0; i < 4; ++i) {
        const int r = m0 + wm*64 + i*16 + g;
        #pragma unroll
        for (int j = 0; j < 4; ++j) {
            const int c = n0 + wn*32 + j*8 + 2*q;
            *(float2*)&C[(size_t)(moff + r)*NCH + c] =
                make_float2(acc[i][j][0], acc[i][j][1]);
            *(float2*)&C[(size_t)(moff + r + 8)*NCH + c] =
                make_float2(acc[i][j][2], acc[i][j][3]);
        }
    }
}

// ---------------- fp32 -> fp16 conversion ---------------------------------
__global__ void __launch_bounds__(256) conv_half(
    const float4* __restrict__ in, uint2* __restrict__ out, int n4)
{
    int i = blockIdx.x*256 + threadIdx.x;
    if (i < n4) {
        float4 v = in[i];
        uint2 o;
        o.x = h2b(__floats2half2_rn(v.x, v.y));
        o.y = h2b(__floats2half2_rn(v.z, v.w));
        out[i] = o;
    }
}

// ---------------- attention core (fp16 tensor-core) ------------------------
// grid (8, 128), 256 threads (8 warps: 4 m-tiles x 2 n-halves).
// smem half tiles stride 72 halves (36 words): frag banks (4g+q)&31 distinct.
#define AH 72
__global__ void __launch_bounds__(256, 2) attn_mma(
    const __half* __restrict__ Kh, const __half* __restrict__ Vh,
    const float* __restrict__ LQ, float* __restrict__ Part)
{
    extern __shared__ __half smh[];
    __half* qs = smh;                    // [64][72] q   (l, d)
    __half* Ks = smh + 64*AH;            // [64][72] K   (c, d)
    __half* Vt = smh + 2*64*AH;          // [64][72] V^T (d, c)
    __half* Ph = smh + 3*64*AH;          // [64][72] P   (l, c)
    float*  Sf = (float*)(smh + 4*64*AH);// [64][68] scores fp32

    const int tid  = threadIdx.x;
    const int lane = tid & 31, warp = tid >> 5;
    const int bh   = blockIdx.y;
    const int b    = bh >> 4, h = bh & 15;
    const int gx   = blockIdx.x;
    const int wm   = warp & 3;
    const int wn   = warp >> 2;
    const int g    = lane >> 2, q = lane & 3;
    const int mr0  = wm*16;
    const int nb   = wn*32;

    const uint32_t* qw = (const uint32_t*)qs;
    const uint32_t* Kw = (const uint32_t*)Ks;
    const uint32_t* Vw = (const uint32_t*)Vt;
    const uint32_t* Pw = (const uint32_t*)Ph;

    #pragma unroll
    for (int it = 0; it < 16; ++it) {
        int e = tid + it*256;
        int l = e >> 6, d = e & 63;
        qs[l*AH + d] = __float2half(LQ[(size_t)(l*NH + h)*ND + d]);
    }

    float accO[4][4];
    #pragma unroll
    for (int j = 0; j < 4; ++j)
        #pragma unroll
        for (int k = 0; k < 4; ++k) accO[j][k] = 0.f;

    __syncthreads();

    for (int nn = 0; nn < 4; ++nn) {
        const int n = gx*4 + nn;
        const size_t rowbase = ((size_t)(b*NCHK + n)*64)*NCH + (size_t)h*ND;

        #pragma unroll
        for (int it = 0; it < 16; ++it) {
            int e = tid + it*256;
            int c = e >> 6, d = e & 63;
            Ks[c*AH + d] = Kh[rowbase + (size_t)c*NCH + d];
        }
        #pragma unroll
        for (int it = 0; it < 16; ++it) {
            int e = tid + it*256;
            int c = e >> 6, d = e & 63;
            Vt[d*AH + c] = Vh[rowbase + (size_t)c*NCH + d];
        }
        __syncthreads();

        // S = q @ K^T  (m=l, n=c, k=d), 4 k16 steps
        float accS[4][4];
        #pragma unroll
        for (int j = 0; j < 4; ++j)
            #pragma unroll
            for (int k = 0; k < 4; ++k) accS[j][k] = 0.f;
        #pragma unroll
        for (int kk = 0; kk < 4; ++kk) {
            const int kw = kk*8;
            const uint32_t a0 = qw[(mr0+g  )*36 + kw + q];
            const uint32_t a1 = qw[(mr0+g+8)*36 + kw + q];
            const uint32_t a2 = qw[(mr0+g  )*36 + kw + q + 4];
            const uint32_t a3 = qw[(mr0+g+8)*36 + kw + q + 4];
            #pragma unroll
            for (int j = 0; j < 4; ++j) {
                const int nr = nb + j*8 + g;
                mma16(accS[j], a0, a1, a2, a3,
                      Kw[nr*36 + kw + q], Kw[nr*36 + kw + q + 4]);
            }
        }
        #pragma unroll
        for (int j = 0; j < 4; ++j) {
            const int c = nb + j*8 + 2*q;
            *(float2*)&Sf[(mr0+g  )*68 + c] =
                make_float2(accS[j][0]*0.125f, accS[j][1]*0.125f);
            *(float2*)&Sf[(mr0+g+8)*68 + c] =
                make_float2(accS[j][2]*0.125f, accS[j][3]*0.125f);
        }
        __syncthreads();

        // masked softmax (8 rows/warp), P -> fp16
        #pragma unroll
        for (int rr = 0; rr < 8; ++rr) {
            const int l = warp*8 + rr;
            float v0 = Sf[l*68 + lane];
            float v1 = Sf[l*68 + 32 + lane];
            const bool m0 = (lane <= l);
            const bool m1 = (32 + lane <= l);
            float mx = fmaxf(m0 ? v0 : -1e30f, m1 ? v1 : -1e30f);
            #pragma unroll
            for (int o = 16; o; o >>= 1) mx = fmaxf(mx, __shfl_xor_sync(~0u, mx, o));
            float e0 = m0 ? expf(v0 - mx) : 0.f;
            float e1 = m1 ? expf(v1 - mx) : 0.f;
            float sm = e0 + e1;
            #pragma unroll
            for (int o = 16; o; o >>= 1) sm += __shfl_xor_sync(~0u, sm, o);
            float r = 1.0f / sm;
            Ph[l*AH + lane]      = __float2half(e0*r);
            Ph[l*AH + 32 + lane] = __float2half(e1*r);
        }
        __syncthreads();

        // O += P @ V  (m=l, n=d, k=c)
        #pragma unroll
        for (int kk = 0; kk < 4; ++kk) {
            const int kw = kk*8;
            const uint32_t a0 = Pw[(mr0+g  )*36 + kw + q];
            const uint32_t a1 = Pw[(mr0+g+8)*36 + kw + q];
            const uint32_t a2 = Pw[(mr0+g  )*36 + kw + q + 4];
            const uint32_t a3 = Pw[(mr0+g+8)*36 + kw + q + 4];
            #pragma unroll
            for (int j = 0; j < 4; ++j) {
                const int nr = nb + j*8 + g;
                mma16(accO[j], a0, a1, a2, a3,
                      Vw[nr*36 + kw + q], Vw[nr*36 + kw + q + 4]);
            }
        }
        __syncthreads();
    }

    const size_t obase = ((size_t)(gx*128 + bh))*4096;
    #pragma unroll
    for (int j = 0; j < 4; ++j) {
        const int d = nb + j*8 + 2*q;
        *(float2*)&Part[obase + (mr0+g  )*64 + d] =
            make_float2(accO[j][0], accO[j][1]);
        *(float2*)&Part[obase + (mr0+g+8)*64 + d] =
            make_float2(accO[j][2], accO[j][3]);
    }
}

// ---------------- U kernel (fused partial reduce, fp16 out) ----------------
__global__ void __launch_bounds__(256) u_kernel(
    const float* __restrict__ Part, const float* __restrict__ Wp,
    __half* __restrict__ Ut)
{
    extern __shared__ float us[];
    float4* As4 = (float4*)us;             // 64 x 17 float4
    float4* Ws4 = (float4*)(us + 64*68);   // 128 x 17 float4

    const int tid  = threadIdx.x;
    const int cblk = blockIdx.x;
    const int bh   = blockIdx.y;
    const int b    = bh >> 4, h = bh & 15;

    const float4* Pf = (const float4*)Part;
    #pragma unroll
    for (int it = 0; it < 4; ++it) {
        int e = tid + it*256;
        int l = e >> 4, d4 = e & 15;
        float4 s = make_float4(0.f, 0.f, 0.f, 0.f);
        #pragma unroll
        for (int gp = 0; gp < 8; ++gp) {
            float4 v = Pf[(size_t)(gp*128 + bh)*1024 + e];
            s.x += v.x; s.y += v.y; s.z += v.z; s.w += v.w;
        }
        As4[l*17 + d4] = s;
    }
    const float4* Wf = (const float4*)Wp;
    #pragma unroll
    for (int it = 0; it < 8; ++it) {
        int e = tid + it*256;
        int cl = e >> 4, d4 = e & 15;
        Ws4[cl*17 + d4] = Wf[(size_t)(cblk*128 + cl)*256 + h*16 + d4];
    }
    __syncthreads();

    const int cg = tid >> 4;
    const int lg = tid & 15;
    float acc[8][4];
    #pragma unroll
    for (int i = 0; i < 8; ++i)
        #pragma unroll
        for (int j = 0; j < 4; ++j) acc[i][j] = 0.f;

    #pragma unroll 4
    for (int d4 = 0; d4 < 16; ++d4) {
        float4 a[4], w[8];
        #pragma unroll
        for (int j = 0; j < 4; ++j) a[j] = As4[(lg*4 + j)*17 + d4];
        #pragma unroll
        for (int i = 0; i < 8; ++i) w[i] = Ws4[(cg*8 + i)*17 + d4];
        #pragma unroll
        for (int i = 0; i < 8; ++i)
            #pragma unroll
            for (int j = 0; j < 4; ++j)
                acc[i][j] += w[i].x*a[j].x + w[i].y*a[j].y
                           + w[i].z*a[j].z + w[i].w*a[j].w;
    }

    #pragma unroll
    for (int i = 0; i < 8; ++i) {
        const int c = cblk*128 + cg*8 + i;
        uint2 u;
        u.x = h2b(__floats2half2_rn(acc[i][0], acc[i][1]));
        u.y = h2b(__floats2half2_rn(acc[i][2], acc[i][3]));
        *reinterpret_cast<uint2*>(
            Ut + (size_t)b*1048576 + (size_t)c*1024 + h*64 + lg*4) = u;
    }
}

// ---------------- launch ---------------------------------------------------
extern "C" void kernel_launch(void* const* d_in, const int* in_sizes, int n_in,
                              void* d_out, int out_size)
{
    const float* x   = (const float*)d_in[0];
    const float* lq  = (const float*)d_in[1];
    const float* W_k = (const float*)d_in[2];
    const float* W_v = (const float*)d_in[3];
    const float* W_g = (const float*)d_in[4];
    const float* W_p = (const float*)d_in[5];
    float* out = (float*)d_out;

    float *Part;
    __half *Kh, *Vh, *Gh, *Uth, *xh, *Wh;
    cudaGetSymbolAddress((void**)&Kh,   g_Kh);
    cudaGetSymbolAddress((void**)&Vh,   g_Vh);
    cudaGetSymbolAddress((void**)&Gh,   g_Gh);
    cudaGetSymbolAddress((void**)&Uth,  g_Uth);
    cudaGetSymbolAddress((void**)&xh,   g_xh);
    cudaGetSymbolAddress((void**)&Wh,   g_Wh);
    cudaGetSymbolAddress((void**)&Part, g_attn_part);

    const int SMEM = 3 * STG;   // 96 KB -> 2 CTAs/SM
    cudaFuncSetAttribute(gemm_tc<3>, cudaFuncAttributeMaxDynamicSharedMemorySize, SMEM);
    cudaFuncSetAttribute(gemm_tc<4>, cudaFuncAttributeMaxDynamicSharedMemorySize, SMEM);
    cudaFuncSetAttribute(gemm_tc<5>, cudaFuncAttributeMaxDynamicSharedMemorySize, SMEM);
    const int ASMEM = 4*64*AH*2 + 64*68*4;    // 54272 B
    cudaFuncSetAttribute(attn_mma, cudaFuncAttributeMaxDynamicSharedMemorySize, ASMEM);
    const int USMEM = (64*68 + 128*68) * 4;   // 52224 B
    cudaFuncSetAttribute(u_kernel, cudaFuncAttributeMaxDynamicSharedMemorySize, USMEM);

    // fp32 -> fp16 conversion
    conv_half<<<32768, 256>>>((const float4*)x,   (uint2*)xh,               8388608);
    conv_half<<<1024, 256>>>((const float4*)W_g, (uint2*)(Wh + 2*1048576), 262144);
    conv_half<<<1024, 256>>>((const float4*)W_k, (uint2*)(Wh + 0*1048576), 262144);
    conv_half<<<1024, 256>>>((const float4*)W_v, (uint2*)(Wh + 1*1048576), 262144);

    // GEMMs (fp16 tensor cores)
    gemm_tc<4><<<dim3(8, 256),    256, SMEM>>>(xh, Wh + 2*1048576, Gh, nullptr);  // gates
    gemm_tc<5><<<dim3(8, 128, 2), 256, SMEM>>>(xh, Wh,             Kh, Vh);       // K(rope)+V

    // attention path (fp16 tensor-core)
    attn_mma<<<dim3(8, 128), 256, ASMEM>>>(Kh, Vh, lq, Part);
    u_kernel<<<dim3(8, 128), 256, USMEM>>>(Part, W_p, Uth);

    // out[b*4096+t][c] = sum_{hl} gates[row][hl] * Ut[b][c][hl]
    gemm_tc<3><<<dim3(8, 32, 8), 256, SMEM>>>(Gh, Uth, out, nullptr);
}